// round 1
// baseline (speedup 1.0000x reference)
#include <cuda_runtime.h>
#include <math.h>

// ---------------------------------------------------------------------------
// Problem constants (fixed by setup_inputs): B=16, D=8, S=256, L=512
//   x    [16, 8, 256, 512]  fp32
//   Wqkv [1536, 512]        fp32
//   bqkv [1536]             fp32
//   n    int32 scalar (256)
// Outputs concatenated into d_out:
//   output            [16, 2048, 512]   -> 16,777,216 floats at offset 0
//   output_matrix_attn [16, 2048, 2048] -> 67,108,864 floats after it
// ---------------------------------------------------------------------------

#define BM 128
#define BN 128
#define BK 16
#define TM 8
#define TN 8

// qkv scratch: [32768, 1536] fp32 = 201 MB (static __device__, no allocation)
static __device__ float g_qkv[50331648];

// ---------------------------------------------------------------------------
// Generic batched tiled SGEMM:
//   C[m,n] = alpha * sum_k A[m,k] * B(n,k)  (+ bias[n])
// B_KMAJOR=true : B indexed B[n*ldb + k]   (C = A * B^T, both K-major)
// B_KMAJOR=false: B indexed B[k*ldb + n]   (C = A * B)
// Batch offset: z = blockIdx.z, zq = z/8, zr = z%8; ptr += zq*O + zr*I
// Requires M % 128 == 0 (grid.y), N % 128 == 0 (grid.x), K % 16 == 0.
// ---------------------------------------------------------------------------
template <bool B_KMAJOR>
__global__ __launch_bounds__(256) void gemm_tiled(
    const float* __restrict__ A, int lda, long long Ao, long long Ai,
    const float* __restrict__ B, int ldb, long long Bo, long long Bi,
    float* __restrict__ C, int ldc, long long Co, long long Ci,
    const float* __restrict__ bias, float alpha, int K)
{
    const long long zq = blockIdx.z >> 3;
    const long long zr = blockIdx.z & 7;
    A += zq * Ao + zr * Ai;
    B += zq * Bo + zr * Bi;
    C += zq * Co + zr * Ci;

    __shared__ float As[BK][BM];
    __shared__ float Bs[BK][BN];

    const int tid  = threadIdx.x;
    const int brow = blockIdx.y * BM;
    const int bcol = blockIdx.x * BN;
    const int tr   = (tid >> 4) * TM;
    const int tc   = (tid & 15) * TN;

    float acc[TM][TN];
#pragma unroll
    for (int i = 0; i < TM; i++)
#pragma unroll
        for (int j = 0; j < TN; j++) acc[i][j] = 0.0f;

    for (int k0 = 0; k0 < K; k0 += BK) {
        // Load A tile: 128 rows x 16 k, K-major, float4 loads
#pragma unroll
        for (int i = 0; i < 2; i++) {
            int idx = tid + i * 256;
            int r   = idx >> 2;
            int c4  = (idx & 3) << 2;
            float4 v = *(const float4*)(A + (long long)(brow + r) * lda + (k0 + c4));
            As[c4 + 0][r] = v.x;
            As[c4 + 1][r] = v.y;
            As[c4 + 2][r] = v.z;
            As[c4 + 3][r] = v.w;
        }
        if (B_KMAJOR) {
#pragma unroll
            for (int i = 0; i < 2; i++) {
                int idx = tid + i * 256;
                int r   = idx >> 2;        // n within tile
                int c4  = (idx & 3) << 2;  // k within tile
                float4 v = *(const float4*)(B + (long long)(bcol + r) * ldb + (k0 + c4));
                Bs[c4 + 0][r] = v.x;
                Bs[c4 + 1][r] = v.y;
                Bs[c4 + 2][r] = v.z;
                Bs[c4 + 3][r] = v.w;
            }
        } else {
#pragma unroll
            for (int i = 0; i < 2; i++) {
                int idx = tid + i * 256;
                int kk  = idx >> 5;        // 0..15
                int nn  = (idx & 31) << 2; // 0..124
                *(float4*)&Bs[kk][nn] =
                    *(const float4*)(B + (long long)(k0 + kk) * ldb + (bcol + nn));
            }
        }
        __syncthreads();

#pragma unroll
        for (int kk = 0; kk < BK; kk++) {
            float a[TM], bb[TN];
#pragma unroll
            for (int i = 0; i < TM; i++) a[i] = As[kk][tr + i];
#pragma unroll
            for (int j = 0; j < TN; j++) bb[j] = Bs[kk][tc + j];
#pragma unroll
            for (int i = 0; i < TM; i++)
#pragma unroll
                for (int j = 0; j < TN; j++)
                    acc[i][j] = fmaf(a[i], bb[j], acc[i][j]);
        }
        __syncthreads();
    }

#pragma unroll
    for (int i = 0; i < TM; i++) {
        float* crow = C + (long long)(brow + tr + i) * ldc + (bcol + tc);
#pragma unroll
        for (int j = 0; j < TN; j += 4) {
            float4 v;
            v.x = acc[i][j + 0] * alpha;
            v.y = acc[i][j + 1] * alpha;
            v.z = acc[i][j + 2] * alpha;
            v.w = acc[i][j + 3] * alpha;
            if (bias) {
                v.x += bias[bcol + tc + j + 0];
                v.y += bias[bcol + tc + j + 1];
                v.z += bias[bcol + tc + j + 2];
                v.w += bias[bcol + tc + j + 3];
            }
            *(float4*)(crow + j) = v;
        }
    }
}

// ---------------------------------------------------------------------------
// Zero-fill (float4 grid-stride)
// ---------------------------------------------------------------------------
__global__ void fill_zero_kernel(float4* __restrict__ p, long long n4)
{
    long long i      = (long long)blockIdx.x * blockDim.x + threadIdx.x;
    long long stride = (long long)gridDim.x * blockDim.x;
    float4 z = make_float4(0.f, 0.f, 0.f, 0.f);
    for (; i < n4; i += stride) p[i] = z;
}

// ---------------------------------------------------------------------------
// Softmax + post-softmax mask, in place on the diagonal blocks of out_mat.
// One warp per row. Row (b, d, s) lives at
//   out_mat + (b*2048 + d*256 + s)*2048 + d*256, 256 contiguous floats.
// Mask: zero where ds==0 or (ds>=1 and ds*n <= 256)  [m=L=512 fixed]
// ---------------------------------------------------------------------------
__global__ __launch_bounds__(256) void softmax_mask_kernel(
    float* __restrict__ out_mat, const int* __restrict__ n_ptr)
{
    const int gwarp = ((blockIdx.x * blockDim.x) + threadIdx.x) >> 5;
    const int lane  = threadIdx.x & 31;
    const int s  = gwarp & 255;
    const int bd = gwarp >> 8;
    const int d  = bd & 7;
    const int b  = bd >> 3;

    float* row = out_mat + ((long long)(b * 2048 + d * 256 + s)) * 2048 + d * 256;

    float vals[8];
    float maxv = -INFINITY;
#pragma unroll
    for (int i = 0; i < 8; i++) {
        vals[i] = row[lane + i * 32];
        maxv = fmaxf(maxv, vals[i]);
    }
#pragma unroll
    for (int off = 16; off; off >>= 1)
        maxv = fmaxf(maxv, __shfl_xor_sync(0xFFFFFFFFu, maxv, off));

    float sum = 0.0f;
#pragma unroll
    for (int i = 0; i < 8; i++) {
        vals[i] = expf(vals[i] - maxv);
        sum += vals[i];
    }
#pragma unroll
    for (int off = 16; off; off >>= 1)
        sum += __shfl_xor_sync(0xFFFFFFFFu, sum, off);

    const float inv = 1.0f / sum;
    const int n = *n_ptr;
#pragma unroll
    for (int i = 0; i < 8; i++) {
        int t  = lane + i * 32;
        int ds = abs(t - s);
        // masked_fill(mask, 0) AFTER softmax: mask true iff ds==0 or ratio in [0.5,1)
        bool masked = (ds == 0) || (ds >= 1 && (long long)ds * n <= 256);
        row[t] = masked ? 0.0f : vals[i] * inv;
    }
}

// ---------------------------------------------------------------------------
extern "C" void kernel_launch(void* const* d_in, const int* in_sizes, int n_in,
                              void* d_out, int out_size)
{
    const float* x  = (const float*)d_in[0];   // [32768, 512] flattened
    const float* W  = (const float*)d_in[1];   // [1536, 512]
    const float* bq = (const float*)d_in[2];   // [1536]
    const int* n_p  = (const int*)d_in[3];     // scalar n

    float* out     = (float*)d_out;            // [16, 2048, 512]
    float* out_mat = out + 16777216LL;         // [16, 2048, 2048]

    float* qkv = nullptr;
    cudaGetSymbolAddress((void**)&qkv, g_qkv); // symbol lookup, not stream work

    // 1) zero the block-diagonal attention matrix (268 MB)
    fill_zero_kernel<<<8192, 256>>>((float4*)out_mat, 16777216LL);

    // 2) QKV projection: qkv[m,f] = x[m,:]·W[f,:] + b[f]
    //    M=32768, N=1536, K=512
    gemm_tiled<true><<<dim3(12, 256, 1), 256>>>(
        x,   512, 0LL, 0LL,
        W,   512, 0LL, 0LL,
        qkv, 1536, 0LL, 0LL,
        bq, 1.0f, 512);

    // 3) scores = Q·K^T / sqrt(512), written straight into diag blocks of out_mat
    //    per (b,d): M=256, N=256, K=512; z = b*8+d
    gemm_tiled<true><<<dim3(2, 2, 128), 256>>>(
        qkv,        1536, 3145728LL, 393216LL,   // Q slab
        qkv + 512,  1536, 3145728LL, 393216LL,   // K slab
        out_mat,    2048, 4194304LL, 524544LL,   // diag block (b,d)
        nullptr, 0.044194173824159216f, 512);

    // 4) softmax rows in place + post-softmax tridiagonal mask
    softmax_mask_kernel<<<4096, 256>>>(out_mat, n_p);

    // 5) out = attn · V : per (b,d): M=256, N=512, K=256, B indexed [k,n]
    gemm_tiled<false><<<dim3(4, 2, 128), 256>>>(
        out_mat,     2048, 4194304LL, 524544LL,  // attn (diag blocks)
        qkv + 1024,  1536, 3145728LL, 393216LL,  // V slab
        out,          512, 1048576LL, 131072LL,  // output[b, d*256+s, l]
        nullptr, 1.0f, 256);
}

// round 4
// speedup vs baseline: 2.0994x; 2.0994x over previous
#include <cuda_runtime.h>
#include <cuda_fp16.h>
#include <stdint.h>
#include <math.h>

// ---------------------------------------------------------------------------
// B=16, D=8, S=256, L=512.
//   x [32768,512] f32 | Wqkv [1536,512] | bqkv [1536] | n (int)
// d_out: output [16,2048,512] (16,777,216 f32) then out_mat [16,2048,2048].
//
// GEMMs run on legacy tensor cores: mma.sync.m16n8k16 fp16 with 2-way
// split-precision (hi+lo) -> 3 HMMAs per logical MMA, fp32-grade accuracy.
// ---------------------------------------------------------------------------

static __device__ float g_qk[33554432];   // [32768][1024]  Q | K
static __device__ float g_vt[16777216];   // [128 z][512 l][256 t]  V^T per (b,d)

// ---------------- smem layout (bytes, dynamic) -------------------------------
// A_hi: half2[128][18] @ 0 (9216) | A_lo @ 9216 | B_hi @ 18432 | B_lo @ 27648
// vpath staging: float[128][129] @ 0 (66048), reused after compute
#define SMEM_BYTES 66560
#define PAD 18

#define MMA_F16(d, a0, a1, a2, a3, b0, b1)                                     \
    asm volatile(                                                              \
        "mma.sync.aligned.m16n8k16.row.col.f32.f16.f16.f32 "                   \
        "{%0,%1,%2,%3},{%4,%5,%6,%7},{%8,%9},{%0,%1,%2,%3};"                   \
        : "+f"((d)[0]), "+f"((d)[1]), "+f"((d)[2]), "+f"((d)[3])               \
        : "r"(a0), "r"(a1), "r"(a2), "r"(a3), "r"(b0), "r"(b1))

struct GP {
    const float* A; int lda; long long Ao, Ai;
    const float* B; int ldb; long long Bo, Bi;
    float*       C; int ldc; long long Co, Ci;
    const float* bias;
    float alpha;
    int K;
    int mode;     // 0 = plain, 1 = QKV (bias; bcol>=1024 tiles -> vt transposed)
    float* vt;
};

__device__ __forceinline__ void split_store(__half2* hi, __half2* lo, int idx,
                                            float x, float y)
{
    __half hx = __float2half_rn(x), hy = __float2half_rn(y);
    hi[idx] = __halves2half2(hx, hy);
    lo[idx] = __halves2half2(__float2half_rn(x - __half2float(hx)),
                             __float2half_rn(y - __half2float(hy)));
}

// ---------------------------------------------------------------------------
__global__ __launch_bounds__(256, 2) void gemm_tc(GP P)
{
    extern __shared__ char smem[];
    __half2* Ah = (__half2*)(smem);
    __half2* Al = (__half2*)(smem + 9216);
    __half2* Bh = (__half2*)(smem + 18432);
    __half2* Bl = (__half2*)(smem + 27648);

    const int tid = threadIdx.x, lane = tid & 31, wid = tid >> 5;
    const int gid = lane >> 2, tig = lane & 3;
    const int wm = wid & 3, wn = wid >> 2;

    const long long zq = blockIdx.z >> 3, zr = blockIdx.z & 7;
    const float* A = P.A + zq * P.Ao + zr * P.Ai;
    const float* B = P.B + zq * P.Bo + zr * P.Bi;
    float*       C = P.C + zq * P.Co + zr * P.Ci;
    const int brow = blockIdx.y * 128, bcol = blockIdx.x * 128;

    float acc[2][8][4];
#pragma unroll
    for (int i = 0; i < 2; i++)
#pragma unroll
        for (int j = 0; j < 8; j++)
#pragma unroll
            for (int q = 0; q < 4; q++) acc[i][j][q] = 0.0f;

    const int NC = P.K >> 5;     // chunks of 32 k
    for (int c = 0; c < NC; c++) {
        // ---- load + split-convert A and B tiles (K-major) ----
        // 128 rows x 8 float4-groups = 1024 units; 256 threads -> 4 iterations
        {
            const float* gA = A + (long long)brow * P.lda + c * 32;
            const float* gB = B + (long long)bcol * P.ldb + c * 32;
#pragma unroll
            for (int i = 0; i < 4; i++) {
                int flat = tid + i * 256;
                int r = flat >> 3, c4 = flat & 7;      // r: row, c4: group of 4 k
                float4 va = *(const float4*)(gA + (long long)r * P.lda + c4 * 4);
                int idx = r * PAD + c4 * 2;            // half2 index
                split_store(Ah, Al, idx,     va.x, va.y);
                split_store(Ah, Al, idx + 1, va.z, va.w);
                float4 vb = *(const float4*)(gB + (long long)r * P.ldb + c4 * 4);
                split_store(Bh, Bl, idx,     vb.x, vb.y);
                split_store(Bh, Bl, idx + 1, vb.z, vb.w);
            }
        }
        __syncthreads();

        // ---- compute: 2 k16 steps ----
#pragma unroll
        for (int ks = 0; ks < 2; ks++) {
            const int kp = ks * 8 + tig;
            uint32_t aH[2][4], aL[2][4];
#pragma unroll
            for (int mi = 0; mi < 2; mi++) {
                int r = wm * 32 + mi * 16 + gid;
                aH[mi][0] = *(uint32_t*)&Ah[r * PAD + kp];
                aH[mi][1] = *(uint32_t*)&Ah[(r + 8) * PAD + kp];
                aH[mi][2] = *(uint32_t*)&Ah[r * PAD + kp + 4];
                aH[mi][3] = *(uint32_t*)&Ah[(r + 8) * PAD + kp + 4];
                aL[mi][0] = *(uint32_t*)&Al[r * PAD + kp];
                aL[mi][1] = *(uint32_t*)&Al[(r + 8) * PAD + kp];
                aL[mi][2] = *(uint32_t*)&Al[r * PAD + kp + 4];
                aL[mi][3] = *(uint32_t*)&Al[(r + 8) * PAD + kp + 4];
            }
#pragma unroll
            for (int j = 0; j < 8; j++) {
                int n = wn * 64 + j * 8 + gid;
                uint32_t b0h = *(uint32_t*)&Bh[n * PAD + kp];
                uint32_t b1h = *(uint32_t*)&Bh[n * PAD + kp + 4];
                uint32_t b0l = *(uint32_t*)&Bl[n * PAD + kp];
                uint32_t b1l = *(uint32_t*)&Bl[n * PAD + kp + 4];
#pragma unroll
                for (int mi = 0; mi < 2; mi++) {
                    MMA_F16(acc[mi][j], aH[mi][0], aH[mi][1], aH[mi][2], aH[mi][3], b0h, b1h);
                    MMA_F16(acc[mi][j], aH[mi][0], aH[mi][1], aH[mi][2], aH[mi][3], b0l, b1l);
                    MMA_F16(acc[mi][j], aL[mi][0], aL[mi][1], aL[mi][2], aL[mi][3], b0h, b1h);
                }
            }
        }
        __syncthreads();
    }

    // ---------------- epilogue ----------------
    const bool vpath = (P.mode == 1) && (bcol >= 1024);
    if (!vpath) {
#pragma unroll
        for (int mi = 0; mi < 2; mi++) {
#pragma unroll
            for (int j = 0; j < 8; j++) {
                int rl  = wm * 32 + mi * 16 + gid;
                int col = wn * 64 + j * 8 + tig * 2;
                float bx = 0.f, by = 0.f;
                if (P.bias) { bx = P.bias[bcol + col]; by = P.bias[bcol + col + 1]; }
                float2 v0 = make_float2(acc[mi][j][0] * P.alpha + bx,
                                        acc[mi][j][1] * P.alpha + by);
                float2 v1 = make_float2(acc[mi][j][2] * P.alpha + bx,
                                        acc[mi][j][3] * P.alpha + by);
                *(float2*)(C + (long long)(brow + rl) * P.ldc + bcol + col)     = v0;
                *(float2*)(C + (long long)(brow + rl + 8) * P.ldc + bcol + col) = v1;
            }
        }
    } else {
        // V tile: bias-add, transpose via smem, write into vt[z][l][t]
        float* st = (float*)smem;           // [128][129]
        __syncthreads();
#pragma unroll
        for (int mi = 0; mi < 2; mi++) {
#pragma unroll
            for (int j = 0; j < 8; j++) {
                int rl  = wm * 32 + mi * 16 + gid;
                int col = wn * 64 + j * 8 + tig * 2;
                float bx = P.bias[bcol + col], by = P.bias[bcol + col + 1];
                st[rl * 129 + col]           = acc[mi][j][0] + bx;
                st[rl * 129 + col + 1]       = acc[mi][j][1] + by;
                st[(rl + 8) * 129 + col]     = acc[mi][j][2] + bx;
                st[(rl + 8) * 129 + col + 1] = acc[mi][j][3] + by;
            }
        }
        __syncthreads();
        const int z2 = brow >> 8;
        const int t0 = brow & 255;
        float* vt = P.vt + (long long)z2 * 131072 + (long long)(bcol - 1024) * 256 + t0;
        for (int idx = tid; idx < 16384; idx += 256) {
            int l = idx >> 7, m = idx & 127;
            vt[(long long)l * 256 + m] = st[m * 129 + l];
        }
    }
}

// ---------------------------------------------------------------------------
__global__ void fill_zero_kernel(float4* __restrict__ p, long long n4)
{
    long long i = (long long)blockIdx.x * blockDim.x + threadIdx.x;
    long long stride = (long long)gridDim.x * blockDim.x;
    float4 z = make_float4(0.f, 0.f, 0.f, 0.f);
    for (; i < n4; i += stride) p[i] = z;
}

// ---------------------------------------------------------------------------
__global__ __launch_bounds__(256) void softmax_mask_kernel(
    float* __restrict__ out_mat, const int* __restrict__ n_ptr)
{
    const int gwarp = ((blockIdx.x * blockDim.x) + threadIdx.x) >> 5;
    const int lane  = threadIdx.x & 31;
    const int s  = gwarp & 255;
    const int bd = gwarp >> 8;
    const int d  = bd & 7;
    const int b  = bd >> 3;

    float* row = out_mat + ((long long)(b * 2048 + d * 256 + s)) * 2048 + d * 256;

    float vals[8];
    float maxv = -INFINITY;
#pragma unroll
    for (int i = 0; i < 8; i++) {
        vals[i] = row[lane + i * 32];
        maxv = fmaxf(maxv, vals[i]);
    }
#pragma unroll
    for (int off = 16; off; off >>= 1)
        maxv = fmaxf(maxv, __shfl_xor_sync(0xFFFFFFFFu, maxv, off));

    float sum = 0.0f;
#pragma unroll
    for (int i = 0; i < 8; i++) { vals[i] = expf(vals[i] - maxv); sum += vals[i]; }
#pragma unroll
    for (int off = 16; off; off >>= 1)
        sum += __shfl_xor_sync(0xFFFFFFFFu, sum, off);

    const float inv = 1.0f / sum;
    const int n = *n_ptr;
#pragma unroll
    for (int i = 0; i < 8; i++) {
        int t  = lane + i * 32;
        int ds = abs(t - s);
        bool masked = (ds == 0) || (ds >= 1 && (long long)ds * n <= 256);
        row[t] = masked ? 0.0f : vals[i] * inv;
    }
}

// ---------------------------------------------------------------------------
extern "C" void kernel_launch(void* const* d_in, const int* in_sizes, int n_in,
                              void* d_out, int out_size)
{
    const float* x  = (const float*)d_in[0];
    const float* W  = (const float*)d_in[1];
    const float* bq = (const float*)d_in[2];
    const int* n_p  = (const int*)d_in[3];

    float* out     = (float*)d_out;
    float* out_mat = out + 16777216LL;

    float *qk = nullptr, *vt = nullptr;
    cudaGetSymbolAddress((void**)&qk, g_qk);
    cudaGetSymbolAddress((void**)&vt, g_vt);

    cudaFuncSetAttribute(gemm_tc, cudaFuncAttributeMaxDynamicSharedMemorySize, SMEM_BYTES);

    // 1) zero out_mat (268 MB)
    fill_zero_kernel<<<8192, 256>>>((float4*)out_mat, 16777216LL);

    // 2) QKV: Q|K -> g_qk [32768,1024], V -> g_vt transposed
    {
        GP P;
        P.A = x;  P.lda = 512;  P.Ao = 0; P.Ai = 0;
        P.B = W;  P.ldb = 512;  P.Bo = 0; P.Bi = 0;
        P.C = qk; P.ldc = 1024; P.Co = 0; P.Ci = 0;
        P.bias = bq; P.alpha = 1.0f; P.K = 512; P.mode = 1; P.vt = vt;
        gemm_tc<<<dim3(12, 256, 1), 256, SMEM_BYTES>>>(P);
    }

    // 3) scores = Q K^T / sqrt(512) -> diagonal blocks of out_mat
    {
        GP P;
        P.A = qk;       P.lda = 1024; P.Ao = 8LL * 262144; P.Ai = 262144;
        P.B = qk + 512; P.ldb = 1024; P.Bo = 8LL * 262144; P.Bi = 262144;
        P.C = out_mat;  P.ldc = 2048; P.Co = 4194304;      P.Ci = 524544;
        P.bias = nullptr; P.alpha = 0.044194173824159216f; P.K = 512;
        P.mode = 0; P.vt = nullptr;
        gemm_tc<<<dim3(2, 2, 128), 256, SMEM_BYTES>>>(P);
    }

    // 4) softmax + post-softmax mask in place
    softmax_mask_kernel<<<4096, 256>>>(out_mat, n_p);

    // 5) out = attn * V   (B = vt, K-major over t)
    {
        GP P;
        P.A = out_mat; P.lda = 2048; P.Ao = 4194304;       P.Ai = 524544;
        P.B = vt;      P.ldb = 256;  P.Bo = 8LL * 131072;  P.Bi = 131072;
        P.C = out;     P.ldc = 512;  P.Co = 1048576;       P.Ci = 131072;
        P.bias = nullptr; P.alpha = 1.0f; P.K = 256;
        P.mode = 0; P.vt = nullptr;
        gemm_tc<<<dim3(4, 2, 128), 256, SMEM_BYTES>>>(P);
    }
}

// round 5
// speedup vs baseline: 2.3191x; 1.1046x over previous
#include <cuda_runtime.h>
#include <cuda_fp16.h>
#include <stdint.h>
#include <math.h>

// ---------------------------------------------------------------------------
// B=16, D=8, S=256, L=512.
//   x [32768,512] f32 | Wqkv [1536,512] | bqkv [1536] | n (int)
// d_out: output [16,2048,512] (16,777,216 f32) then out_mat [16,2048,2048].
//
// All GEMMs: legacy mma.sync.m16n8k16 fp16 with 2-way split precision
// (hi+lo, 3 HMMAs per logical MMA). All operands pre-split to half planes,
// cp.async double-buffered tiles.
// ---------------------------------------------------------------------------

static __device__ __half g_xs [2][16777216];  // x split planes [32768*512]
static __device__ __half g_ws [2][786432];    // Wqkv split planes [1536*512]
static __device__ __half g_qks[2][33554432];  // Q|K split [32768*1024]
static __device__ __half g_vts[2][16777216];  // V^T split [128 z][512 l][256 t]
static __device__ __half g_as [2][8388608];   // attn split [128 z][256 s][256 t]

// ---------------- smem: 2 stages x 4 planes(half2[128][20]) ------------------
// plane = 10240B; stage = 40960B; total 81920B. vpath f32 staging reuses it.
#define PAD 20
#define PLANE 10240
#define STAGE 40960
#define SMEM_BYTES 81920

#define MMA_F16(d, a0, a1, a2, a3, b0, b1)                                     \
    asm volatile(                                                              \
        "mma.sync.aligned.m16n8k16.row.col.f32.f16.f16.f32 "                   \
        "{%0,%1,%2,%3},{%4,%5,%6,%7},{%8,%9},{%0,%1,%2,%3};"                   \
        : "+f"((d)[0]), "+f"((d)[1]), "+f"((d)[2]), "+f"((d)[3])               \
        : "r"(a0), "r"(a1), "r"(a2), "r"(a3), "r"(b0), "r"(b1))

#define CP16(dst, src)                                                         \
    asm volatile("cp.async.cg.shared.global [%0], [%1], 16;"                   \
                 :: "r"(dst), "l"(src))
#define CP_COMMIT() asm volatile("cp.async.commit_group;" ::: "memory")
#define CP_WAIT(n)  asm volatile("cp.async.wait_group %0;" :: "n"(n) : "memory")

__device__ __forceinline__ uint32_t smem_u32(const void* p) {
    uint32_t a;
    asm("{ .reg .u64 t; cvta.to.shared.u64 t, %1; cvt.u32.u64 %0, t; }" : "=r"(a) : "l"(p));
    return a;
}

struct GP {
    const __half *Ah, *Al; int lda; long long Ao, Ai;
    const __half *Bh, *Bl; int ldb; long long Bo, Bi;
    float* C; int ldc; long long Co, Ci;        // mode 0 output
    __half *Ch, *Cl;                            // mode 1: Q|K split output
    __half *vth, *vtl;                          // mode 1: V^T split output
    const float* bias;
    float alpha;
    int K;
    int mode;     // 0 = f32 C; 1 = QKV (split C; bcol>=1024 -> vt transposed)
};

// ---------------------------------------------------------------------------
__global__ __launch_bounds__(256, 2) void gemm_tc(GP P)
{
    extern __shared__ char smem[];
    const uint32_t sb = smem_u32(smem);

    const int tid = threadIdx.x, lane = tid & 31, wid = tid >> 5;
    const int gid = lane >> 2, tig = lane & 3;
    const int wm = wid & 3, wn = wid >> 2;

    const long long zq = blockIdx.z >> 3, zr = blockIdx.z & 7;
    const __half* Ah = P.Ah + zq * P.Ao + zr * P.Ai;
    const __half* Al = P.Al + zq * P.Ao + zr * P.Ai;
    const __half* Bh = P.Bh + zq * P.Bo + zr * P.Bi;
    const __half* Bl = P.Bl + zq * P.Bo + zr * P.Bi;
    const int brow = blockIdx.y * 128, bcol = blockIdx.x * 128;

    // per-thread cp.async coordinates: 512 16B-units per plane, 2 per thread
    const int u0r = tid >> 2,         u0s = tid & 3;          // unit tid
    const int u1r = (tid + 256) >> 2, u1s = tid & 3;          // unit tid+256

    float acc[2][8][4];
#pragma unroll
    for (int i = 0; i < 2; i++)
#pragma unroll
        for (int j = 0; j < 8; j++)
#pragma unroll
            for (int q = 0; q < 4; q++) acc[i][j][q] = 0.0f;

    const __half* gAh = Ah + (long long)brow * P.lda;
    const __half* gAl = Al + (long long)brow * P.lda;
    const __half* gBh = Bh + (long long)bcol * P.ldb;
    const __half* gBl = Bl + (long long)bcol * P.ldb;

    const int NC = P.K >> 5;

    // ---- chunk loader: stage p <- chunk c ----
    auto load_chunk = [&](int c, int p) {
        const uint32_t st = sb + p * STAGE;
        const int k0 = c * 32;
        // unit 0
        {
            uint32_t d = st + u0r * 80 + u0s * 16;
            long long ga = (long long)u0r * P.lda + k0 + u0s * 8;
            long long gb = (long long)u0r * P.ldb + k0 + u0s * 8;
            CP16(d,              gAh + ga);
            CP16(d + PLANE,      gAl + ga);
            CP16(d + 2 * PLANE,  gBh + gb);
            CP16(d + 3 * PLANE,  gBl + gb);
        }
        // unit 1
        {
            uint32_t d = st + u1r * 80 + u1s * 16;
            long long ga = (long long)u1r * P.lda + k0 + u1s * 8;
            long long gb = (long long)u1r * P.ldb + k0 + u1s * 8;
            CP16(d,              gAh + ga);
            CP16(d + PLANE,      gAl + ga);
            CP16(d + 2 * PLANE,  gBh + gb);
            CP16(d + 3 * PLANE,  gBl + gb);
        }
        CP_COMMIT();
    };

    load_chunk(0, 0);

    for (int c = 0; c < NC; c++) {
        const int p = c & 1;
        if (c + 1 < NC) { load_chunk(c + 1, p ^ 1); CP_WAIT(1); }
        else            { CP_WAIT(0); }
        __syncthreads();

        const __half2* Ahs = (const __half2*)(smem + p * STAGE);
        const __half2* Als = (const __half2*)(smem + p * STAGE + PLANE);
        const __half2* Bhs = (const __half2*)(smem + p * STAGE + 2 * PLANE);
        const __half2* Bls = (const __half2*)(smem + p * STAGE + 3 * PLANE);

#pragma unroll
        for (int ks = 0; ks < 2; ks++) {
            const int kp = ks * 8 + tig;
            uint32_t aH[2][4], aL[2][4];
#pragma unroll
            for (int mi = 0; mi < 2; mi++) {
                int r = wm * 32 + mi * 16 + gid;
                aH[mi][0] = *(const uint32_t*)&Ahs[r * PAD + kp];
                aH[mi][1] = *(const uint32_t*)&Ahs[(r + 8) * PAD + kp];
                aH[mi][2] = *(const uint32_t*)&Ahs[r * PAD + kp + 4];
                aH[mi][3] = *(const uint32_t*)&Ahs[(r + 8) * PAD + kp + 4];
                aL[mi][0] = *(const uint32_t*)&Als[r * PAD + kp];
                aL[mi][1] = *(const uint32_t*)&Als[(r + 8) * PAD + kp];
                aL[mi][2] = *(const uint32_t*)&Als[r * PAD + kp + 4];
                aL[mi][3] = *(const uint32_t*)&Als[(r + 8) * PAD + kp + 4];
            }
#pragma unroll
            for (int j = 0; j < 8; j++) {
                int n = wn * 64 + j * 8 + gid;
                uint32_t b0h = *(const uint32_t*)&Bhs[n * PAD + kp];
                uint32_t b1h = *(const uint32_t*)&Bhs[n * PAD + kp + 4];
                uint32_t b0l = *(const uint32_t*)&Bls[n * PAD + kp];
                uint32_t b1l = *(const uint32_t*)&Bls[n * PAD + kp + 4];
#pragma unroll
                for (int mi = 0; mi < 2; mi++) {
                    MMA_F16(acc[mi][j], aH[mi][0], aH[mi][1], aH[mi][2], aH[mi][3], b0h, b1h);
                    MMA_F16(acc[mi][j], aH[mi][0], aH[mi][1], aH[mi][2], aH[mi][3], b0l, b1l);
                    MMA_F16(acc[mi][j], aL[mi][0], aL[mi][1], aL[mi][2], aL[mi][3], b0h, b1h);
                }
            }
        }
        __syncthreads();
    }

    // ---------------- epilogue ----------------
    if (P.mode == 0) {
        float* C = P.C + zq * P.Co + zr * P.Ci;
#pragma unroll
        for (int mi = 0; mi < 2; mi++) {
#pragma unroll
            for (int j = 0; j < 8; j++) {
                int rl  = wm * 32 + mi * 16 + gid;
                int col = wn * 64 + j * 8 + tig * 2;
                float2 v0 = make_float2(acc[mi][j][0] * P.alpha, acc[mi][j][1] * P.alpha);
                float2 v1 = make_float2(acc[mi][j][2] * P.alpha, acc[mi][j][3] * P.alpha);
                *(float2*)(C + (long long)(brow + rl) * P.ldc + bcol + col)     = v0;
                *(float2*)(C + (long long)(brow + rl + 8) * P.ldc + bcol + col) = v1;
            }
        }
    } else if (bcol < 1024) {
        // Q|K tile -> split halves into Ch/Cl (ldc = 1024)
#pragma unroll
        for (int mi = 0; mi < 2; mi++) {
#pragma unroll
            for (int j = 0; j < 8; j++) {
                int rl  = wm * 32 + mi * 16 + gid;
                int col = wn * 64 + j * 8 + tig * 2;
                float bx = P.bias[bcol + col], by = P.bias[bcol + col + 1];
#pragma unroll
                for (int h = 0; h < 2; h++) {
                    float v0 = acc[mi][j][2 * h + 0] + bx;
                    float v1 = acc[mi][j][2 * h + 1] + by;
                    __half h0 = __float2half_rn(v0), h1 = __float2half_rn(v1);
                    long long o = (long long)(brow + rl + 8 * h) * 1024 + bcol + col;
                    *(__half2*)(P.Ch + o) = __halves2half2(h0, h1);
                    *(__half2*)(P.Cl + o) = __halves2half2(
                        __float2half_rn(v0 - __half2float(h0)),
                        __float2half_rn(v1 - __half2float(h1)));
                }
            }
        }
    } else {
        // V tile: bias-add, transpose via f32 smem staging, split into vth/vtl
        float* st = (float*)smem;           // [128][129] = 66048B
        __syncthreads();
#pragma unroll
        for (int mi = 0; mi < 2; mi++) {
#pragma unroll
            for (int j = 0; j < 8; j++) {
                int rl  = wm * 32 + mi * 16 + gid;
                int col = wn * 64 + j * 8 + tig * 2;
                float bx = P.bias[bcol + col], by = P.bias[bcol + col + 1];
                st[rl * 129 + col]           = acc[mi][j][0] + bx;
                st[rl * 129 + col + 1]       = acc[mi][j][1] + by;
                st[(rl + 8) * 129 + col]     = acc[mi][j][2] + bx;
                st[(rl + 8) * 129 + col + 1] = acc[mi][j][3] + by;
            }
        }
        __syncthreads();
        const int z2 = brow >> 8;
        const int t0 = brow & 255;
        long long base = (long long)z2 * 131072 + (long long)(bcol - 1024) * 256 + t0;
        for (int idx = tid; idx < 16384; idx += 256) {
            int l = idx >> 7, m = idx & 127;
            float v = st[m * 129 + l];
            __half h = __float2half_rn(v);
            long long o = base + (long long)l * 256 + m;
            P.vth[o] = h;
            P.vtl[o] = __float2half_rn(v - __half2float(h));
        }
    }
}

// ---------------------------------------------------------------------------
__global__ void split_kernel(const float* __restrict__ src,
                             __half* __restrict__ hi, __half* __restrict__ lo,
                             int n4)
{
    int i = blockIdx.x * blockDim.x + threadIdx.x;
    if (i >= n4) return;
    float4 v = ((const float4*)src)[i];
    __half h0 = __float2half_rn(v.x), h1 = __float2half_rn(v.y);
    __half h2 = __float2half_rn(v.z), h3 = __float2half_rn(v.w);
    ((__half2*)hi)[2 * i]     = __halves2half2(h0, h1);
    ((__half2*)hi)[2 * i + 1] = __halves2half2(h2, h3);
    ((__half2*)lo)[2 * i]     = __halves2half2(
        __float2half_rn(v.x - __half2float(h0)),
        __float2half_rn(v.y - __half2float(h1)));
    ((__half2*)lo)[2 * i + 1] = __halves2half2(
        __float2half_rn(v.z - __half2float(h2)),
        __float2half_rn(v.w - __half2float(h3)));
}

// ---------------------------------------------------------------------------
__global__ void fill_zero_kernel(float4* __restrict__ p, long long n4)
{
    long long i = (long long)blockIdx.x * blockDim.x + threadIdx.x;
    long long stride = (long long)gridDim.x * blockDim.x;
    float4 z = make_float4(0.f, 0.f, 0.f, 0.f);
    for (; i < n4; i += stride) p[i] = z;
}

// ---------------------------------------------------------------------------
// Softmax + post-softmax mask; writes f32 attn into out_mat diag blocks AND
// split halves into g_as planes.
__global__ __launch_bounds__(256) void softmax_mask_kernel(
    float* __restrict__ out_mat, const int* __restrict__ n_ptr,
    __half* __restrict__ ah, __half* __restrict__ al)
{
    const int gwarp = ((blockIdx.x * blockDim.x) + threadIdx.x) >> 5;
    const int lane  = threadIdx.x & 31;
    const int s  = gwarp & 255;
    const int bd = gwarp >> 8;
    const int d  = bd & 7;
    const int b  = bd >> 3;

    float* row = out_mat + ((long long)(b * 2048 + d * 256 + s)) * 2048 + d * 256;
    long long abase = (long long)bd * 65536 + (long long)s * 256;

    float vals[8];
    float maxv = -INFINITY;
#pragma unroll
    for (int i = 0; i < 8; i++) {
        vals[i] = row[lane + i * 32];
        maxv = fmaxf(maxv, vals[i]);
    }
#pragma unroll
    for (int off = 16; off; off >>= 1)
        maxv = fmaxf(maxv, __shfl_xor_sync(0xFFFFFFFFu, maxv, off));

    float sum = 0.0f;
#pragma unroll
    for (int i = 0; i < 8; i++) { vals[i] = expf(vals[i] - maxv); sum += vals[i]; }
#pragma unroll
    for (int off = 16; off; off >>= 1)
        sum += __shfl_xor_sync(0xFFFFFFFFu, sum, off);

    const float inv = 1.0f / sum;
    const int n = *n_ptr;
#pragma unroll
    for (int i = 0; i < 8; i++) {
        int t  = lane + i * 32;
        int ds = abs(t - s);
        bool masked = (ds == 0) || (ds >= 1 && (long long)ds * n <= 256);
        float v = masked ? 0.0f : vals[i] * inv;
        row[t] = v;
        __half h = __float2half_rn(v);
        ah[abase + t] = h;
        al[abase + t] = __float2half_rn(v - __half2float(h));
    }
}

// ---------------------------------------------------------------------------
extern "C" void kernel_launch(void* const* d_in, const int* in_sizes, int n_in,
                              void* d_out, int out_size)
{
    const float* x  = (const float*)d_in[0];
    const float* W  = (const float*)d_in[1];
    const float* bq = (const float*)d_in[2];
    const int* n_p  = (const int*)d_in[3];

    float* out     = (float*)d_out;
    float* out_mat = out + 16777216LL;

    __half *xs0, *xs1, *ws0, *ws1, *qk0, *qk1, *vt0, *vt1, *as0, *as1;
    cudaGetSymbolAddress((void**)&xs0, g_xs);  xs1 = xs0 + 16777216;
    cudaGetSymbolAddress((void**)&ws0, g_ws);  ws1 = ws0 + 786432;
    cudaGetSymbolAddress((void**)&qk0, g_qks); qk1 = qk0 + 33554432;
    cudaGetSymbolAddress((void**)&vt0, g_vts); vt1 = vt0 + 16777216;
    cudaGetSymbolAddress((void**)&as0, g_as);  as1 = as0 + 8388608;

    cudaFuncSetAttribute(gemm_tc, cudaFuncAttributeMaxDynamicSharedMemorySize, SMEM_BYTES);

    // 0) split x and W into half planes
    split_kernel<<<16384, 256>>>(x, xs0, xs1, 4194304);
    split_kernel<<<768, 256>>>(W, ws0, ws1, 196608);

    // 1) zero out_mat (268 MB)
    fill_zero_kernel<<<8192, 256>>>((float4*)out_mat, 16777216LL);

    // 2) QKV: Q|K -> g_qks split, V -> g_vts split transposed
    {
        GP P = {};
        P.Ah = xs0; P.Al = xs1; P.lda = 512;  P.Ao = 0; P.Ai = 0;
        P.Bh = ws0; P.Bl = ws1; P.ldb = 512;  P.Bo = 0; P.Bi = 0;
        P.Ch = qk0; P.Cl = qk1;
        P.vth = vt0; P.vtl = vt1;
        P.bias = bq; P.alpha = 1.0f; P.K = 512; P.mode = 1;
        gemm_tc<<<dim3(12, 256, 1), 256, SMEM_BYTES>>>(P);
    }

    // 3) scores = Q K^T / sqrt(512) -> diagonal blocks of out_mat (f32)
    {
        GP P = {};
        P.Ah = qk0;       P.Al = qk1;       P.lda = 1024; P.Ao = 8LL * 262144; P.Ai = 262144;
        P.Bh = qk0 + 512; P.Bl = qk1 + 512; P.ldb = 1024; P.Bo = 8LL * 262144; P.Bi = 262144;
        P.C = out_mat; P.ldc = 2048; P.Co = 4194304; P.Ci = 524544;
        P.alpha = 0.044194173824159216f; P.K = 512; P.mode = 0;
        gemm_tc<<<dim3(2, 2, 128), 256, SMEM_BYTES>>>(P);
    }

    // 4) softmax + mask; writes f32 attn + split-half attn
    softmax_mask_kernel<<<4096, 256>>>(out_mat, n_p, as0, as1);

    // 5) out = attn * V   (A = split attn, B = split V^T, both K-major over t)
    {
        GP P = {};
        P.Ah = as0; P.Al = as1; P.lda = 256; P.Ao = 8LL * 65536;  P.Ai = 65536;
        P.Bh = vt0; P.Bl = vt1; P.ldb = 256; P.Bo = 8LL * 131072; P.Bi = 131072;
        P.C = out; P.ldc = 512; P.Co = 1048576; P.Ci = 131072;
        P.alpha = 1.0f; P.K = 256; P.mode = 0;
        gemm_tc<<<dim3(4, 2, 128), 256, SMEM_BYTES>>>(P);
    }
}